// round 9
// baseline (speedup 1.0000x reference)
#include <cuda_runtime.h>
#include <cuda_bf16.h>

// PixCorr: mean over rows of per-row Pearson correlation between
// preds[n,:] and targets[n,:], each row D = 3*256*256 = 196608 fp32.
// Pure HBM-streaming (~402 MB read).
//
// Persistent kernel, 296 blocks (= 148 SMs x 2, exactly one wave). Work is
// 2048 chunks (8 per row, ~0.196 MB each) distributed via a dynamic atomic
// work queue -- no static grid can balance this (total work = 2^22*3 float4,
// any multiple of 148 has a factor 37). Chunk ids are prefetched one ahead
// so the atomic latency hides under streaming. Per-chunk sufficient
// statistics go to chunk-indexed slots (deterministic regardless of which
// block processes which chunk). Last block to arrive reduces the partials,
// computes per-row correlations + mean, writes out, resets counters.

static constexpr int NROWS   = 256;
static constexpr int D_ELEMS = 3 * 256 * 256;        // 196608
static constexpr int D4      = D_ELEMS / 4;          // 49152 float4 per row
static constexpr int CPR     = 8;                    // chunks per row
static constexpr int NCHUNKS = NROWS * CPR;          // 2048
static constexpr int CHUNK4  = D4 / CPR;             // 6144 float4 per chunk
static constexpr int GRID    = 296;                  // 148 SMs x 2
static constexpr int TPB     = 1024;                 // 6 float4 iters/chunk

// Scratch (device allocation forbidden). Counters reset by the elected
// last block at the end of every call -> graph-replayable.
__device__ float        g_part[NCHUNKS * 5];
__device__ unsigned int g_work;
__device__ unsigned int g_done;

__global__ void __launch_bounds__(TPB, 2)
pixcorr_persistent_kernel(const float* __restrict__ preds,
                          const float* __restrict__ targets,
                          float* __restrict__ out)
{
    const float4* __restrict__ zbase = reinterpret_cast<const float4*>(targets);
    const float4* __restrict__ bbase = reinterpret_cast<const float4*>(preds);

    const int warp = threadIdx.x >> 5;
    const int lane = threadIdx.x & 31;

    __shared__ float sm[5][32];
    __shared__ int   sh_next[2];

    // First grab.
    if (threadIdx.x == 0)
        sh_next[0] = (int)atomicAdd(&g_work, 1u);
    __syncthreads();
    int cur = sh_next[0];
    int parity = 1;

    while (cur < NCHUNKS) {
        // Prefetch next chunk id (latency hides under ~8us of streaming).
        if (threadIdx.x == 0)
            sh_next[parity] = (int)atomicAdd(&g_work, 1u);

        const int row = cur >> 3;            // cur / CPR
        const int sub = cur & 7;             // cur % CPR
        const size_t base = (size_t)row * D4 + (size_t)sub * CHUNK4;
        const float4* __restrict__ zp = zbase + base;
        const float4* __restrict__ bp = bbase + base;

        float sz = 0.f, sb = 0.f, szz = 0.f, sbb = 0.f, szb = 0.f;

        #pragma unroll 3
        for (int i = threadIdx.x; i < CHUNK4; i += TPB) {
            const float4 zv = zp[i];
            const float4 bv = bp[i];
            sz  += (zv.x + zv.y) + (zv.z + zv.w);
            sb  += (bv.x + bv.y) + (bv.z + bv.w);
            szz += zv.x * zv.x + zv.y * zv.y + zv.z * zv.z + zv.w * zv.w;
            sbb += bv.x * bv.x + bv.y * bv.y + bv.z * bv.z + bv.w * bv.w;
            szb += zv.x * bv.x + zv.y * bv.y + zv.z * bv.z + zv.w * bv.w;
        }

        // Warp reduce all 5 accumulators.
        #pragma unroll
        for (int o = 16; o > 0; o >>= 1) {
            sz  += __shfl_xor_sync(0xffffffffu, sz,  o);
            sb  += __shfl_xor_sync(0xffffffffu, sb,  o);
            szz += __shfl_xor_sync(0xffffffffu, szz, o);
            sbb += __shfl_xor_sync(0xffffffffu, sbb, o);
            szb += __shfl_xor_sync(0xffffffffu, szb, o);
        }
        if (lane == 0) {
            sm[0][warp] = sz;  sm[1][warp] = sb;  sm[2][warp] = szz;
            sm[3][warp] = sbb; sm[4][warp] = szb;
        }
        __syncthreads();   // publishes sm[] AND sh_next[parity]

        if (warp == 0) {
            sz  = sm[0][lane]; sb  = sm[1][lane]; szz = sm[2][lane];
            sbb = sm[3][lane]; szb = sm[4][lane];
            #pragma unroll
            for (int o = 16; o > 0; o >>= 1) {
                sz  += __shfl_xor_sync(0xffffffffu, sz,  o);
                sb  += __shfl_xor_sync(0xffffffffu, sb,  o);
                szz += __shfl_xor_sync(0xffffffffu, szz, o);
                sbb += __shfl_xor_sync(0xffffffffu, sbb, o);
                szb += __shfl_xor_sync(0xffffffffu, szb, o);
            }
            if (lane == 0) {
                float* p = &g_part[cur * 5];
                p[0] = sz; p[1] = sb; p[2] = szz; p[3] = sbb; p[4] = szb;
            }
        }

        cur = sh_next[parity];
        parity ^= 1;
        __syncthreads();   // sm[] fully consumed before next chunk reuses it
    }

    // ── Last-block-done election ──────────────────────────────────────────
    __shared__ bool is_last;
    if (threadIdx.x == 0) {
        __threadfence();                  // publish g_part writes GPU-wide
        unsigned int old = atomicAdd(&g_done, 1u);
        is_last = (old == GRID - 1);
    }
    __syncthreads();
    if (!is_last) return;

    // ── Final stage: threads 0..255 each own one row ──────────────────────
    float corr = 0.f;
    if (threadIdx.x < NROWS) {
        const int r = threadIdx.x;
        float tsz = 0.f, tsb = 0.f, tszz = 0.f, tsbb = 0.f, tszb = 0.f;
        #pragma unroll
        for (int c = 0; c < CPR; c++) {
            const float* p = &g_part[(r * CPR + c) * 5];
            tsz += p[0]; tsb += p[1]; tszz += p[2]; tsbb += p[3]; tszb += p[4];
        }
        const float invD = 1.0f / (float)D_ELEMS;
        const float num  = tszb - tsz * tsb * invD;
        const float vz   = fmaxf(tszz - tsz * tsz * invD, 0.0f);
        const float vb   = fmaxf(tsbb - tsb * tsb * invD, 0.0f);
        const float den  = sqrtf(vz) * sqrtf(vb) + 1e-6f;
        corr = num / den;
    }

    // Mean over rows (only warps 0..7 hold nonzero values).
    #pragma unroll
    for (int o = 16; o > 0; o >>= 1)
        corr += __shfl_xor_sync(0xffffffffu, corr, o);
    if (lane == 0) sm[0][warp] = corr;
    __syncthreads();
    if (threadIdx.x < 8) {
        float v = sm[0][threadIdx.x];
        #pragma unroll
        for (int o = 4; o > 0; o >>= 1)
            v += __shfl_xor_sync(0x000000ffu, v, o);
        if (threadIdx.x == 0) {
            out[0] = v * (1.0f / (float)NROWS);
            g_work = 0;                   // reset for next graph replay
            g_done = 0;
        }
    }
}

extern "C" void kernel_launch(void* const* d_in, const int* in_sizes, int n_in,
                              void* d_out, int out_size)
{
    const float* preds   = (const float*)d_in[0];
    const float* targets = (const float*)d_in[1];
    float* out = (float*)d_out;

    pixcorr_persistent_kernel<<<GRID, TPB>>>(preds, targets, out);
}